// round 5
// baseline (speedup 1.0000x reference)
#include <cuda_runtime.h>
#include <math.h>

#define BB 64
#define NN 8732
#define CC 81
#define TN 64                       // anchors per conf tile
#define TPR ((NN + TN - 1) / TN)    // 137 tiles per row
#define NT (BB * TPR)               // 8768 tiles
#define NU4 (NN / 4)                // 2183 uint4 per key row
#define PADN 9216                   // NN padded to 9*1024

// Scratch (device globals — no runtime allocation). Every word is written each
// launch before being read: deterministic, no init kernel.
__device__ unsigned g_keys[BB * NN];     // pos -> 0, else float bits of conf_loss
__device__ unsigned char g_cnt[NT];      // per-tile positive count
__device__ float g_psum[NT];             // per-tile sum of positive conf_loss
__device__ float g_locpart[NT];          // per-tile loc loss partial

// conf loss + key + per-tile partials + loc partial. One 64-anchor tile/block.
// gt_conf is exactly one-hot => every anchor has exactly ONE nonzero element,
// so s_dot/s_posb have a unique writer each: no init, no atomics.
__global__ __launch_bounds__(256) void conf_kernel(const float* __restrict__ pc,
                                                   const float* __restrict__ gc,
                                                   const float* __restrict__ pl,
                                                   const float* __restrict__ gl) {
    __shared__ float se[TN * CC];            // exp(pred_conf) tile (20736 B)
    __shared__ float s_dot[TN];              // x[label] per anchor
    __shared__ unsigned char s_posb[TN];     // 1 if label != 0
    __shared__ float s_wps[8];
    __shared__ int s_wcnt[8];

    const int tid = threadIdx.x;
    const int tile = blockIdx.x;
    const int b = blockIdx.y;
    const int n0 = tile * TN;
    const int nA = (n0 + TN <= NN) ? TN : (NN - n0);   // 64 or 28 (both %4==0)
    const int n4 = (nA * CC) >> 2;

    const size_t base = ((size_t)b * NN + n0) * CC;    // multiple of 4 floats
    const float4* p4 = (const float4*)(pc + base);
    const float4* g4 = (const float4*)(gc + base);
    for (int i = tid; i < n4; i += 256) {
        const float4 p = p4[i];
        const float4 g = g4[i];
        float4 e;
        e.x = __expf(p.x); e.y = __expf(p.y);
        e.z = __expf(p.z); e.w = __expf(p.w);
        ((float4*)se)[i] = e;                          // stage exp, not x
        if (g.x != 0.0f || g.y != 0.0f || g.z != 0.0f || g.w != 0.0f) {
            const float pv[4] = {p.x, p.y, p.z, p.w};
            const float gv[4] = {g.x, g.y, g.z, g.w};
            #pragma unroll
            for (int j = 0; j < 4; ++j) {
                if (gv[j] != 0.0f) {                   // unique writer per anchor
                    const int f = 4 * i + j;
                    const int a = f / CC;
                    const int cls = f - a * CC;
                    s_dot[a] = pv[j] * gv[j];          // = x[label] (gt value 1.0)
                    s_posb[a] = (cls != 0) ? 1 : 0;
                }
            }
        }
    }
    __syncthreads();

    const int warp = tid >> 5;
    const int lane = tid & 31;
    float psum = 0.0f;
    int pcnt = 0;
    for (int a = warp; a < nA; a += 8) {
        const float* xe = se + a * CC;
        float e = xe[lane] + xe[32 + lane];
        if (lane < 17) e += xe[64 + lane];
        #pragma unroll
        for (int o = 16; o; o >>= 1) e += __shfl_xor_sync(0xFFFFFFFFu, e, o);
        if (lane == 0) {
            const float cl = __logf(e) - s_dot[a];     // lse - x[label] > 0
            const bool pos = s_posb[a];
            g_keys[b * NN + n0 + a] = pos ? 0u : __float_as_uint(cl);
            if (pos) { psum += cl; ++pcnt; }
        }
    }
    if (lane == 0) { s_wps[warp] = psum; s_wcnt[warp] = pcnt; }

    // loc partial: warps 0-1, one anchor (float4 pair) per lane.
    if (warp < 2) {
        const int a = warp * 32 + lane;
        float ls = 0.0f;
        if (a < nA) {
            const float4* plv = (const float4*)(pl + ((size_t)b * NN + n0) * 4);
            const float4* glv = (const float4*)(gl + ((size_t)b * NN + n0) * 4);
            float4 a4 = plv[a];
            float4 g4v = glv[a];
            float d, ad;
            d = a4.x - g4v.x; ad = fabsf(d); if (ad > 1.0f) ls += ad - 0.5f;
            d = a4.y - g4v.y; ad = fabsf(d); if (ad > 1.0f) ls += ad - 0.5f;
            d = a4.z - g4v.z; ad = fabsf(d); if (ad > 1.0f) ls += ad - 0.5f;
            d = a4.w - g4v.w; ad = fabsf(d); if (ad > 1.0f) ls += ad - 0.5f;
        }
        #pragma unroll
        for (int o = 16; o; o >>= 1) ls += __shfl_xor_sync(0xFFFFFFFFu, ls, o);
        if (lane == 0 && warp == 0) s_wps[1] += 0.0f;  // no-op keep layout
        if (lane == 0) s_wcnt[warp] = s_wcnt[warp];    // no-op
        if (lane == 0) {
            if (warp == 0) g_locpart[b * TPR + tile] = ls;  // warp1 adds below
            else atomicAdd(&g_locpart[b * TPR + tile], 0.0f); // placeholder removed
        }
        // NOTE: simple correct scheme: warp0 writes, warp1 adds — replaced below.
    }
    __syncthreads();
    if (tid == 0) {
        float tp = 0.0f; int tc = 0;
        #pragma unroll
        for (int w = 0; w < 8; ++w) { tp += s_wps[w]; tc += s_wcnt[w]; }
        g_psum[b * TPR + tile] = tp;
        g_cnt[b * TPR + tile] = (unsigned char)tc;
    }
}

// Correction kernel-free loc: computed in conf via two-warp partial — but the
// ordering of warp0 write / warp1 add within one block is racy. Use a clean
// variant instead: loc partials per (tile, halfwarp) slot.
// ---- The above placeholder logic is neutralized; real loc below. ----

__global__ __launch_bounds__(256) void loc_fix_kernel(const float* __restrict__ pl,
                                                      const float* __restrict__ gl) {
    // grid (TPR, BB): one tile per block, 64 anchors, warps 0-1 cover them.
    const int tid = threadIdx.x;
    if (tid >= 64) return;
    const int b = blockIdx.y;
    const int n0 = blockIdx.x * TN;
    const int nA = (n0 + TN <= NN) ? TN : (NN - n0);
    float ls = 0.0f;
    if (tid < nA) {
        const float4* plv = (const float4*)(pl + ((size_t)b * NN + n0) * 4);
        const float4* glv = (const float4*)(gl + ((size_t)b * NN + n0) * 4);
        float4 a4 = plv[tid];
        float4 g4v = glv[tid];
        float d, ad;
        d = a4.x - g4v.x; ad = fabsf(d); if (ad > 1.0f) ls += ad - 0.5f;
        d = a4.y - g4v.y; ad = fabsf(d); if (ad > 1.0f) ls += ad - 0.5f;
        d = a4.z - g4v.z; ad = fabsf(d); if (ad > 1.0f) ls += ad - 0.5f;
        d = a4.w - g4v.w; ad = fabsf(d); if (ad > 1.0f) ls += ad - 0.5f;
    }
    #pragma unroll
    for (int o = 16; o; o >>= 1) ls += __shfl_xor_sync(0xFFFFFFFFu, ls, o);
    __shared__ float s2[2];
    if ((tid & 31) == 0) s2[tid >> 5] = ls;
    __syncthreads();
    if (tid == 0) g_locpart[b * TPR + blockIdx.x] = s2[0] + s2[1];
}

// One 1024-thread block per batch row. 3-pass (11/11/10 bit) radix rank-k
// select with stable argsort-index resolution; pass 1 fused into the load.
__global__ __launch_bounds__(1024) void select_kernel(float* __restrict__ out, int half) {
    const int b = blockIdx.x;
    const int tid = threadIdx.x;
    const int lane = tid & 31;
    const int warp = tid >> 5;

    __shared__ __align__(16) unsigned keys[NN];   // 34928 B
    __shared__ int hist[2048];
    __shared__ float s_rf[32], s_rf2[32];
    __shared__ int s_ri[32], s_w[32];
    __shared__ int s_sel, s_want, s_idx, s_k;
    __shared__ float s_ps, s_ls;

    hist[tid] = 0; hist[tid + 1024] = 0;
    __syncthreads();

    // (1) load key row (uint4) + pass-1 histogram (key bits [21,32)).
    const uint4* k4 = (const uint4*)(g_keys + (size_t)b * NN);
    for (int i = tid; i < 3072; i += 1024) {           // uniform 3 iterations
        uint4 v = make_uint4(0u, 0u, 0u, 0u);
        const bool ok = (i < NU4);
        if (ok) { v = k4[i]; ((uint4*)keys)[i] = v; }
        const unsigned kk[4] = {v.x, v.y, v.z, v.w};
        #pragma unroll
        for (int j = 0; j < 4; ++j) {
            const int bj = ok ? (int)(kk[j] >> 21) : -1;
            unsigned m = __match_any_sync(0xFFFFFFFFu, bj);
            if (bj >= 0 && (__ffs(m) - 1) == lane) atomicAdd(&hist[bj], __popc(m));
        }
    }

    // global positive count -> k; row pos-sum and loc-sum from tile partials.
    int c = 0;
    const uchar4* c4 = (const uchar4*)g_cnt;
    for (int i = tid; i < NT / 4; i += 1024) {
        uchar4 u = c4[i];
        c += u.x + u.y + u.z + u.w;
    }
    float ps = 0.0f, lp = 0.0f;
    for (int i = tid; i < TPR; i += 1024) {
        ps += g_psum[b * TPR + i];
        lp += g_locpart[b * TPR + i];
    }
    #pragma unroll
    for (int o = 16; o; o >>= 1) {
        c  += __shfl_xor_sync(0xFFFFFFFFu, c, o);
        ps += __shfl_xor_sync(0xFFFFFFFFu, ps, o);
        lp += __shfl_xor_sync(0xFFFFFFFFu, lp, o);
    }
    if (lane == 0) { s_ri[warp] = c; s_rf[warp] = ps; s_rf2[warp] = lp; }
    __syncthreads();
    if (tid == 0) {
        int tc = 0; float tp = 0.0f, tl = 0.0f;
        #pragma unroll
        for (int w = 0; w < 32; ++w) { tc += s_ri[w]; tp += s_rf[w]; tl += s_rf2[w]; }
        int k = 3 * tc;
        if (k > NN - 1) k = NN - 1;
        if (k < 0) k = 0;
        s_k = k; s_ps = tp; s_ls = tl;
    }
    __syncthreads();

    int want = s_k;

    #define PICK_DIGIT()                                                          \
    {                                                                             \
        const int b0 = hist[2 * tid], b1 = hist[2 * tid + 1];                     \
        const int s = b0 + b1;                                                    \
        int incl = s;                                                             \
        _Pragma("unroll")                                                         \
        for (int o = 1; o < 32; o <<= 1) {                                        \
            int t = __shfl_up_sync(0xFFFFFFFFu, incl, o);                         \
            if (lane >= o) incl += t;                                             \
        }                                                                         \
        if (lane == 31) s_w[warp] = incl;                                         \
        __syncthreads();                                                          \
        if (warp == 0) {                                                          \
            int t = s_w[lane];                                                    \
            int ti = t;                                                           \
            _Pragma("unroll")                                                     \
            for (int o = 1; o < 32; o <<= 1) {                                    \
                int u = __shfl_up_sync(0xFFFFFFFFu, ti, o);                       \
                if (lane >= o) ti += u;                                           \
            }                                                                     \
            s_w[lane] = ti - t;                                                   \
        }                                                                         \
        __syncthreads();                                                          \
        const int excl = s_w[warp] + incl - s;                                    \
        if (want >= excl && want < excl + s) {                                    \
            if (want - excl < b0) { s_sel = 2 * tid; s_want = want - excl; }      \
            else                  { s_sel = 2 * tid + 1; s_want = want - excl - b0; } \
        }                                                                         \
        __syncthreads();                                                          \
    }

    PICK_DIGIT();
    const unsigned pref1 = (unsigned)s_sel;
    want = s_want;
    __syncthreads();

    // pass 2: bits [10,21) — uint4 sweep.
    hist[tid] = 0; hist[tid + 1024] = 0;
    __syncthreads();
    for (int i = tid; i < 3072; i += 1024) {
        uint4 v = make_uint4(0xFFFFFFFFu, 0xFFFFFFFFu, 0xFFFFFFFFu, 0xFFFFFFFFu);
        if (i < NU4) v = ((const uint4*)keys)[i];
        const unsigned kk[4] = {v.x, v.y, v.z, v.w};
        #pragma unroll
        for (int j = 0; j < 4; ++j) {
            const int bin = ((kk[j] >> 21) == pref1) ? (int)((kk[j] >> 10) & 2047) : -1;
            unsigned m = __match_any_sync(0xFFFFFFFFu, bin);
            if (bin >= 0 && (__ffs(m) - 1) == lane) atomicAdd(&hist[bin], __popc(m));
        }
    }
    __syncthreads();
    PICK_DIGIT();
    const unsigned pref2 = (pref1 << 11) | (unsigned)s_sel;
    want = s_want;
    __syncthreads();

    // pass 3: bits [0,10) — uint4 sweep.
    hist[tid] = 0; hist[tid + 1024] = 0;
    __syncthreads();
    for (int i = tid; i < 3072; i += 1024) {
        uint4 v = make_uint4(0xFFFFFFFFu, 0xFFFFFFFFu, 0xFFFFFFFFu, 0xFFFFFFFFu);
        if (i < NU4) v = ((const uint4*)keys)[i];
        const unsigned kk[4] = {v.x, v.y, v.z, v.w};
        #pragma unroll
        for (int j = 0; j < 4; ++j) {
            const int bin = ((kk[j] >> 10) == pref2) ? (int)(kk[j] & 1023) : -1;
            unsigned m = __match_any_sync(0xFFFFFFFFu, bin);
            if (bin >= 0 && (__ffs(m) - 1) == lane) atomicAdd(&hist[bin], __popc(m));
        }
    }
    __syncthreads();
    PICK_DIGIT();
    const unsigned v = (pref2 << 10) | (unsigned)s_sel;
    const int r = s_want;
    #undef PICK_DIGIT

    // resolve original index (stable ascending = jnp.argsort) via block scan.
    const int lo = tid * 9;
    const int hiE = (lo + 9 < NN) ? lo + 9 : NN;
    int cnt = 0;
    for (int n = lo; n < hiE; ++n) if (keys[n] == v) ++cnt;
    int incl = cnt;
    #pragma unroll
    for (int o = 1; o < 32; o <<= 1) {
        int t = __shfl_up_sync(0xFFFFFFFFu, incl, o);
        if (lane >= o) incl += t;
    }
    if (lane == 31) s_w[warp] = incl;
    __syncthreads();
    if (warp == 0) {
        int t = s_w[lane];
        int ti = t;
        #pragma unroll
        for (int o = 1; o < 32; o <<= 1) {
            int u = __shfl_up_sync(0xFFFFFFFFu, ti, o);
            if (lane >= o) ti += u;
        }
        s_w[lane] = ti - t;
    }
    __syncthreads();
    {
        const int excl = s_w[warp] + incl - cnt;
        if (r >= excl && r < excl + cnt) {
            int rr = r - excl;
            for (int n = lo; n < hiE; ++n) {
                if (keys[n] == v) {
                    if (rr == 0) { s_idx = n; break; }
                    --rr;
                }
            }
        }
    }
    __syncthreads();
    const float thr = (float)s_idx;   // the quirk: argsort INDEX as threshold

    // negative conf sum (positives are key 0, auto-excluded since thr >= 0).
    float nsum = 0.0f;
    for (int i = tid; i < NU4; i += 1024) {
        uint4 u = ((const uint4*)keys)[i];
        float f;
        f = __uint_as_float(u.x); if (f > thr) nsum += f;
        f = __uint_as_float(u.y); if (f > thr) nsum += f;
        f = __uint_as_float(u.z); if (f > thr) nsum += f;
        f = __uint_as_float(u.w); if (f > thr) nsum += f;
    }
    #pragma unroll
    for (int o = 16; o; o >>= 1) nsum += __shfl_xor_sync(0xFFFFFFFFu, nsum, o);
    if (lane == 0) s_rf[warp] = nsum;
    __syncthreads();
    if (tid == 0) {
        float t = 0.0f;
        #pragma unroll
        for (int w = 0; w < 32; ++w) t += s_rf[w];
        out[b] = s_ps + t;
        out[half + b] = s_ls;
    }
}

extern "C" void kernel_launch(void* const* d_in, const int* in_sizes, int n_in,
                              void* d_out, int out_size) {
    const int big_sz = BB * NN * CC;
    int ib[2] = {-1, -1}, is[2] = {-1, -1};
    int nb = 0, ns = 0;
    for (int i = 0; i < n_in; ++i) {
        if (in_sizes[i] == big_sz) { if (nb < 2) ib[nb] = i; ++nb; }
        else                       { if (ns < 2) is[ns] = i; ++ns; }
    }
    const float* pred_conf = (const float*)d_in[ib[0]];
    const float* gt_conf   = (const float*)d_in[ib[1]];
    const float* pred_loc  = (const float*)d_in[is[0]];
    const float* gt_loc    = (const float*)d_in[is[1]];
    float* out = (float*)d_out;
    const int half = out_size / 2;

    dim3 gridc(TPR, BB);
    conf_kernel<<<gridc, 256>>>(pred_conf, gt_conf, pred_loc, gt_loc);
    loc_fix_kernel<<<gridc, 64>>>(pred_loc, gt_loc);
    select_kernel<<<BB, 1024>>>(out, half);
}

// round 6
// speedup vs baseline: 1.5832x; 1.5832x over previous
#include <cuda_runtime.h>
#include <math.h>

#define BB 64
#define NN 8732
#define CC 81
#define TN 64                       // anchors per conf tile
#define TPR ((NN + TN - 1) / TN)    // 137 tiles per row
#define NT (BB * TPR)               // 8768 tiles
#define NU4 (NN / 4)                // 2183 uint4 per key row

// Scratch (device globals — no runtime allocation). Every word read is written
// first in the same launch sequence: deterministic, no init kernel.
__device__ unsigned g_keys[BB * NN];     // pos -> 0, else float bits of conf_loss
__device__ unsigned char g_cnt[NT];      // per-tile positive count
__device__ float g_psum[NT];             // per-tile sum of positive conf_loss
__device__ float g_locpart[NT];          // per-tile loc loss partial

// One 64-anchor tile per 256-thread block.
// Phase 1: all threads stage pred_conf tile (float4) and extract the one-hot
//          label info (gt_conf has EXACTLY one nonzero per anchor -> unique
//          writer, no atomics).
// Phase 2: warps 0-1: thread-per-anchor Σexp (conflict-free stride-81 LDS,
//          no shuffles); warps 2-3: loc partial (overlaps with warps 0-1).
__global__ __launch_bounds__(256) void conf_kernel(const float* __restrict__ pc,
                                                   const float* __restrict__ gc,
                                                   const float* __restrict__ pl,
                                                   const float* __restrict__ gl) {
    __shared__ float sx[TN * CC];            // 20736 B raw pred_conf tile
    __shared__ float s_dot[TN];              // x[label] per anchor
    __shared__ unsigned char s_posb[TN];     // 1 if label != 0
    __shared__ float s_ps2[2];
    __shared__ int s_pc2[2];
    __shared__ float s_loc2[2];

    const int tid = threadIdx.x;
    const int lane = tid & 31;
    const int warp = tid >> 5;
    const int tile = blockIdx.x;
    const int b = blockIdx.y;
    const int n0 = tile * TN;
    const int nA = (n0 + TN <= NN) ? TN : (NN - n0);   // 64 or 28 (both %4==0)
    const int n4 = (nA * CC) >> 2;

    const size_t base = ((size_t)b * NN + n0) * CC;    // multiple of 4 floats
    const float4* p4 = (const float4*)(pc + base);
    const float4* g4 = (const float4*)(gc + base);
    for (int i = tid; i < n4; i += 256) {
        const float4 p = p4[i];
        ((float4*)sx)[i] = p;
        const float4 g = g4[i];
        if (g.x != 0.0f || g.y != 0.0f || g.z != 0.0f || g.w != 0.0f) {
            const float pv[4] = {p.x, p.y, p.z, p.w};
            const float gv[4] = {g.x, g.y, g.z, g.w};
            #pragma unroll
            for (int j = 0; j < 4; ++j) {
                if (gv[j] != 0.0f) {                   // unique writer per anchor
                    const int f = 4 * i + j;
                    const int a = f / CC;
                    const int cls = f - a * CC;
                    s_dot[a] = pv[j] * gv[j];          // = x[label] (gt value 1.0)
                    s_posb[a] = (cls != 0) ? 1 : 0;
                }
            }
        }
    }
    __syncthreads();

    if (tid < TN) {
        // thread-per-anchor: lanes access stride-81 rows -> conflict-free.
        float pv = 0.0f;
        int pc_ = 0;
        if (tid < nA) {
            const float* x = sx + tid * CC;
            float e0 = 0.0f, e1 = 0.0f, e2 = 0.0f, e3 = 0.0f;
            #pragma unroll
            for (int c = 0; c < 80; c += 4) {          // 4 indep MUFU chains
                e0 += __expf(x[c]);
                e1 += __expf(x[c + 1]);
                e2 += __expf(x[c + 2]);
                e3 += __expf(x[c + 3]);
            }
            e0 += __expf(x[80]);
            const float cl = __logf((e0 + e1) + (e2 + e3)) - s_dot[tid];
            const bool pos = s_posb[tid];
            g_keys[b * NN + n0 + tid] = pos ? 0u : __float_as_uint(cl);
            if (pos) { pv = cl; pc_ = 1; }
        }
        #pragma unroll
        for (int o = 16; o; o >>= 1) {
            pv  += __shfl_xor_sync(0xFFFFFFFFu, pv, o);
            pc_ += __shfl_xor_sync(0xFFFFFFFFu, pc_, o);
        }
        if (lane == 0) { s_ps2[warp] = pv; s_pc2[warp] = pc_; }
    } else if (tid < 128) {
        // loc partial: one anchor (float4 pair) per lane, warps 2-3.
        const int a = tid - 64;
        float ls = 0.0f;
        if (a < nA) {
            const float4* plv = (const float4*)(pl + ((size_t)b * NN + n0) * 4);
            const float4* glv = (const float4*)(gl + ((size_t)b * NN + n0) * 4);
            const float4 a4 = plv[a];
            const float4 g4v = glv[a];
            float d, ad;
            d = a4.x - g4v.x; ad = fabsf(d); if (ad > 1.0f) ls += ad - 0.5f;
            d = a4.y - g4v.y; ad = fabsf(d); if (ad > 1.0f) ls += ad - 0.5f;
            d = a4.z - g4v.z; ad = fabsf(d); if (ad > 1.0f) ls += ad - 0.5f;
            d = a4.w - g4v.w; ad = fabsf(d); if (ad > 1.0f) ls += ad - 0.5f;
        }
        #pragma unroll
        for (int o = 16; o; o >>= 1) ls += __shfl_xor_sync(0xFFFFFFFFu, ls, o);
        if (lane == 0) s_loc2[warp - 2] = ls;
    }
    __syncthreads();
    if (tid == 0) {
        const int t = b * TPR + tile;
        g_psum[t] = s_ps2[0] + s_ps2[1];
        g_cnt[t] = (unsigned char)(s_pc2[0] + s_pc2[1]);
        g_locpart[t] = s_loc2[0] + s_loc2[1];
    }
}

// One 1024-thread block per batch row. 3-pass (11/11/10 bit) radix rank-k
// select with stable argsort-index resolution; pass 1 fused into the load.
__global__ __launch_bounds__(1024) void select_kernel(float* __restrict__ out, int half) {
    const int b = blockIdx.x;
    const int tid = threadIdx.x;
    const int lane = tid & 31;
    const int warp = tid >> 5;

    __shared__ __align__(16) unsigned keys[NN];   // 34928 B
    __shared__ int hist[2048];
    __shared__ float s_rf[32], s_rf2[32];
    __shared__ int s_ri[32], s_w[32];
    __shared__ int s_sel, s_want, s_idx, s_k;
    __shared__ float s_ps, s_ls;

    hist[tid] = 0; hist[tid + 1024] = 0;
    __syncthreads();

    // (1) load key row (uint4) + pass-1 histogram (key bits [21,32)).
    const uint4* k4 = (const uint4*)(g_keys + (size_t)b * NN);
    for (int i = tid; i < 3072; i += 1024) {           // uniform 3 iterations
        uint4 v = make_uint4(0u, 0u, 0u, 0u);
        const bool ok = (i < NU4);
        if (ok) { v = k4[i]; ((uint4*)keys)[i] = v; }
        const unsigned kk[4] = {v.x, v.y, v.z, v.w};
        #pragma unroll
        for (int j = 0; j < 4; ++j) {
            const int bj = ok ? (int)(kk[j] >> 21) : -1;
            unsigned m = __match_any_sync(0xFFFFFFFFu, bj);
            if (bj >= 0 && (__ffs(m) - 1) == lane) atomicAdd(&hist[bj], __popc(m));
        }
    }

    // global positive count -> k; row pos-sum and loc-sum from tile partials.
    int c = 0;
    const uchar4* c4 = (const uchar4*)g_cnt;
    for (int i = tid; i < NT / 4; i += 1024) {
        uchar4 u = c4[i];
        c += u.x + u.y + u.z + u.w;
    }
    float ps = 0.0f, lp = 0.0f;
    for (int i = tid; i < TPR; i += 1024) {
        ps += g_psum[b * TPR + i];
        lp += g_locpart[b * TPR + i];
    }
    #pragma unroll
    for (int o = 16; o; o >>= 1) {
        c  += __shfl_xor_sync(0xFFFFFFFFu, c, o);
        ps += __shfl_xor_sync(0xFFFFFFFFu, ps, o);
        lp += __shfl_xor_sync(0xFFFFFFFFu, lp, o);
    }
    if (lane == 0) { s_ri[warp] = c; s_rf[warp] = ps; s_rf2[warp] = lp; }
    __syncthreads();
    if (tid == 0) {
        int tc = 0; float tp = 0.0f, tl = 0.0f;
        #pragma unroll
        for (int w = 0; w < 32; ++w) { tc += s_ri[w]; tp += s_rf[w]; tl += s_rf2[w]; }
        int k = 3 * tc;                  // (3.0f * num_pos) -> int32, exact
        if (k > NN - 1) k = NN - 1;
        if (k < 0) k = 0;
        s_k = k; s_ps = tp; s_ls = tl;
    }
    __syncthreads();

    int want = s_k;

    #define PICK_DIGIT()                                                          \
    {                                                                             \
        const int b0 = hist[2 * tid], b1 = hist[2 * tid + 1];                     \
        const int s = b0 + b1;                                                    \
        int incl = s;                                                             \
        _Pragma("unroll")                                                         \
        for (int o = 1; o < 32; o <<= 1) {                                        \
            int t = __shfl_up_sync(0xFFFFFFFFu, incl, o);                         \
            if (lane >= o) incl += t;                                             \
        }                                                                         \
        if (lane == 31) s_w[warp] = incl;                                         \
        __syncthreads();                                                          \
        if (warp == 0) {                                                          \
            int t = s_w[lane];                                                    \
            int ti = t;                                                           \
            _Pragma("unroll")                                                     \
            for (int o = 1; o < 32; o <<= 1) {                                    \
                int u = __shfl_up_sync(0xFFFFFFFFu, ti, o);                       \
                if (lane >= o) ti += u;                                           \
            }                                                                     \
            s_w[lane] = ti - t;                                                   \
        }                                                                         \
        __syncthreads();                                                          \
        const int excl = s_w[warp] + incl - s;                                    \
        if (want >= excl && want < excl + s) {                                    \
            if (want - excl < b0) { s_sel = 2 * tid; s_want = want - excl; }      \
            else                  { s_sel = 2 * tid + 1; s_want = want - excl - b0; } \
        }                                                                         \
        __syncthreads();                                                          \
    }

    PICK_DIGIT();
    const unsigned pref1 = (unsigned)s_sel;            // top 11 bits
    want = s_want;
    __syncthreads();

    // pass 2: bits [10,21) — uint4 sweep.
    hist[tid] = 0; hist[tid + 1024] = 0;
    __syncthreads();
    for (int i = tid; i < 3072; i += 1024) {
        uint4 v = make_uint4(0xFFFFFFFFu, 0xFFFFFFFFu, 0xFFFFFFFFu, 0xFFFFFFFFu);
        if (i < NU4) v = ((const uint4*)keys)[i];
        const unsigned kk[4] = {v.x, v.y, v.z, v.w};
        #pragma unroll
        for (int j = 0; j < 4; ++j) {
            const int bin = ((kk[j] >> 21) == pref1) ? (int)((kk[j] >> 10) & 2047) : -1;
            unsigned m = __match_any_sync(0xFFFFFFFFu, bin);
            if (bin >= 0 && (__ffs(m) - 1) == lane) atomicAdd(&hist[bin], __popc(m));
        }
    }
    __syncthreads();
    PICK_DIGIT();
    const unsigned pref2 = (pref1 << 11) | (unsigned)s_sel;   // top 22 bits
    want = s_want;
    __syncthreads();

    // pass 3: bits [0,10) — uint4 sweep.
    hist[tid] = 0; hist[tid + 1024] = 0;
    __syncthreads();
    for (int i = tid; i < 3072; i += 1024) {
        uint4 v = make_uint4(0xFFFFFFFFu, 0xFFFFFFFFu, 0xFFFFFFFFu, 0xFFFFFFFFu);
        if (i < NU4) v = ((const uint4*)keys)[i];
        const unsigned kk[4] = {v.x, v.y, v.z, v.w};
        #pragma unroll
        for (int j = 0; j < 4; ++j) {
            const int bin = ((kk[j] >> 10) == pref2) ? (int)(kk[j] & 1023) : -1;
            unsigned m = __match_any_sync(0xFFFFFFFFu, bin);
            if (bin >= 0 && (__ffs(m) - 1) == lane) atomicAdd(&hist[bin], __popc(m));
        }
    }
    __syncthreads();
    PICK_DIGIT();
    const unsigned v = (pref2 << 10) | (unsigned)s_sel;       // rank-k key value
    const int r = s_want;                                     // rank among equal keys
    #undef PICK_DIGIT

    // resolve original index (stable ascending = jnp.argsort) via block scan
    // over contiguous per-thread ranges.
    const int lo = tid * 9;                                   // 9*1024 >= NN
    const int hiE = (lo + 9 < NN) ? lo + 9 : NN;
    int cnt = 0;
    for (int n = lo; n < hiE; ++n) if (keys[n] == v) ++cnt;
    int incl = cnt;
    #pragma unroll
    for (int o = 1; o < 32; o <<= 1) {
        int t = __shfl_up_sync(0xFFFFFFFFu, incl, o);
        if (lane >= o) incl += t;
    }
    if (lane == 31) s_w[warp] = incl;
    __syncthreads();
    if (warp == 0) {
        int t = s_w[lane];
        int ti = t;
        #pragma unroll
        for (int o = 1; o < 32; o <<= 1) {
            int u = __shfl_up_sync(0xFFFFFFFFu, ti, o);
            if (lane >= o) ti += u;
        }
        s_w[lane] = ti - t;
    }
    __syncthreads();
    {
        const int excl = s_w[warp] + incl - cnt;
        if (r >= excl && r < excl + cnt) {
            int rr = r - excl;
            for (int n = lo; n < hiE; ++n) {
                if (keys[n] == v) {
                    if (rr == 0) { s_idx = n; break; }
                    --rr;
                }
            }
        }
    }
    __syncthreads();
    const float thr = (float)s_idx;   // the quirk: argsort INDEX as threshold

    // negative conf sum (positives are key 0, auto-excluded since thr >= 0).
    float nsum = 0.0f;
    for (int i = tid; i < NU4; i += 1024) {
        uint4 u = ((const uint4*)keys)[i];
        float f;
        f = __uint_as_float(u.x); if (f > thr) nsum += f;
        f = __uint_as_float(u.y); if (f > thr) nsum += f;
        f = __uint_as_float(u.z); if (f > thr) nsum += f;
        f = __uint_as_float(u.w); if (f > thr) nsum += f;
    }
    #pragma unroll
    for (int o = 16; o; o >>= 1) nsum += __shfl_xor_sync(0xFFFFFFFFu, nsum, o);
    if (lane == 0) s_rf[warp] = nsum;
    __syncthreads();
    if (tid == 0) {
        float t = 0.0f;
        #pragma unroll
        for (int w = 0; w < 32; ++w) t += s_rf[w];
        out[b] = s_ps + t;
        out[half + b] = s_ls;
    }
}

extern "C" void kernel_launch(void* const* d_in, const int* in_sizes, int n_in,
                              void* d_out, int out_size) {
    const int big_sz = BB * NN * CC;
    int ib[2] = {-1, -1}, is[2] = {-1, -1};
    int nb = 0, ns = 0;
    for (int i = 0; i < n_in; ++i) {
        if (in_sizes[i] == big_sz) { if (nb < 2) ib[nb] = i; ++nb; }
        else                       { if (ns < 2) is[ns] = i; ++ns; }
    }
    const float* pred_conf = (const float*)d_in[ib[0]];
    const float* gt_conf   = (const float*)d_in[ib[1]];
    const float* pred_loc  = (const float*)d_in[is[0]];
    const float* gt_loc    = (const float*)d_in[is[1]];
    float* out = (float*)d_out;
    const int half = out_size / 2;

    dim3 gridc(TPR, BB);
    conf_kernel<<<gridc, 256>>>(pred_conf, gt_conf, pred_loc, gt_loc);
    select_kernel<<<BB, 1024>>>(out, half);
}